// round 1
// baseline (speedup 1.0000x reference)
#include <cuda_runtime.h>
#include <cuda_bf16.h>
#include <cstdint>

// Problem constants (fixed by setup_inputs)
#define BB   4
#define CC   128
#define HF   128
#define WF   128
#define NV   10475
#define NT   200000
#define KB   20
#define IMG_H 512
#define IMG_W 512
#define HW   (IMG_H * IMG_W)
#define FHW  (HF * WF)

// Scratch: transposed feature map (B, Hf, Wf, C) and per-batch depth map.
__device__ float    g_fmT[(size_t)BB * FHW * CC];     // 33.5 MB
__device__ unsigned g_depth[(size_t)BB * HW];         // 4 MB

// ---------------------------------------------------------------------------
// Kernel 1: transpose (B,C,Hf*Wf) -> (B,Hf*Wf,C), tiled via smem
// ---------------------------------------------------------------------------
__global__ void transpose_k(const float* __restrict__ fm) {
    __shared__ float tile[32][33];
    const int b  = blockIdx.z;
    const int p0 = blockIdx.x * 32;   // spatial block
    const int c0 = blockIdx.y * 32;   // channel block
    const int tx = threadIdx.x;
    const int ty = threadIdx.y;       // block (32, 8)

    const float* src = fm + (size_t)b * CC * FHW;
#pragma unroll
    for (int i = 0; i < 32; i += 8)
        tile[ty + i][tx] = src[(size_t)(c0 + ty + i) * FHW + (p0 + tx)];
    __syncthreads();
    float* dst = g_fmT + (size_t)b * FHW * CC;
#pragma unroll
    for (int i = 0; i < 32; i += 8)
        dst[(size_t)(p0 + ty + i) * CC + (c0 + tx)] = tile[tx][ty + i];
}

// ---------------------------------------------------------------------------
// Kernel 2: init depth map to +inf
// ---------------------------------------------------------------------------
__global__ void depth_init_k() {
    int i = blockIdx.x * blockDim.x + threadIdx.x;
    if (i < BB * HW) g_depth[i] = 0x7f800000u;  // +inf bits
}

// ---------------------------------------------------------------------------
// Kernel 3: scatter-min z over rounded vertex pixels
// z in [1,5] (positive) -> uint-bit atomicMin == float min
// ---------------------------------------------------------------------------
__global__ void depth_scatter_k(const float* __restrict__ v2d,
                                const float* __restrict__ v3d) {
    int i = blockIdx.x * blockDim.x + threadIdx.x;   // i = b*NV + v
    if (i >= BB * NV) return;
    int b = i / NV;
    float x = v2d[2 * i];
    float y = v2d[2 * i + 1];
    int xi = (int)rintf(x);   // round-half-even, matches jnp.round
    int yi = (int)rintf(y);
    if (xi >= 0 && xi < IMG_W && yi >= 0 && yi < IMG_H) {
        float z = v3d[3 * i + 2];
        atomicMin(&g_depth[(size_t)b * HW + yi * IMG_W + xi], __float_as_uint(z));
    }
}

// ---------------------------------------------------------------------------
// Kernel 4: main — one warp per (b, n)
// ---------------------------------------------------------------------------
__global__ void __launch_bounds__(256)
main_k(const float* __restrict__ v2d,
       const float* __restrict__ v3d,
       const int*   __restrict__ parents,
       const float* __restrict__ bary,
       float* __restrict__ out_feats,   // (B,N,C)
       float* __restrict__ out_vw,      // (B,N)
       float* __restrict__ out_c3)      // (B,N,3)
{
    const int gwarp = (blockIdx.x * blockDim.x + threadIdx.x) >> 5;
    const int lane  = threadIdx.x & 31;
    if (gwarp >= BB * NT) return;
    const int b = gwarp / NT;
    const int n = gwarp - b * NT;

    // --- gather parents + barycentric weights (broadcast loads across lanes)
    const int p0 = __ldg(&parents[3 * n + 0]);
    const int p1 = __ldg(&parents[3 * n + 1]);
    const int p2 = __ldg(&parents[3 * n + 2]);
    const int r  = n % KB;
    const float w0 = __ldg(&bary[3 * r + 0]);
    const float w1 = __ldg(&bary[3 * r + 1]);
    const float w2 = __ldg(&bary[3 * r + 2]);

    const float* v2b = v2d + (size_t)b * NV * 2;
    const float* v3b = v3d + (size_t)b * NV * 3;

    const float2 q0 = *(const float2*)(v2b + 2 * p0);
    const float2 q1 = *(const float2*)(v2b + 2 * p1);
    const float2 q2 = *(const float2*)(v2b + 2 * p2);
    const float cx = w0 * q0.x + w1 * q1.x + w2 * q2.x;
    const float cy = w0 * q0.y + w1 * q1.y + w2 * q2.y;

    const float a0x = v3b[3 * p0], a0y = v3b[3 * p0 + 1], a0z = v3b[3 * p0 + 2];
    const float a1x = v3b[3 * p1], a1y = v3b[3 * p1 + 1], a1z = v3b[3 * p1 + 2];
    const float a2x = v3b[3 * p2], a2y = v3b[3 * p2 + 1], a2z = v3b[3 * p2 + 2];
    const float c3x = w0 * a0x + w1 * a1x + w2 * a2x;
    const float c3y = w0 * a0y + w1 * a1y + w2 * a2y;
    const float c3z = w0 * a0z + w1 * a1z + w2 * a2z;

    // --- face normal & angle weight
    const float e1x = a1x - a0x, e1y = a1y - a0y, e1z = a1z - a0z;
    const float e2x = a2x - a0x, e2y = a2y - a0y, e2z = a2z - a0z;
    float nx = e1y * e2z - e1z * e2y;
    float ny = e1z * e2x - e1x * e2z;
    float nz = e1x * e2y - e1y * e2x;
    const float nl = sqrtf(nx * nx + ny * ny + nz * nz) + 1e-8f;
    nx /= nl; ny /= nl; nz /= nl;
    const float vl = sqrtf(c3x * c3x + c3y * c3y + c3z * c3z) + 1e-8f;
    const float vx = -c3x / vl, vy = -c3y / vl, vz = -c3z / vl;
    const float aw = fmaxf(nx * vx + ny * vy + nz * vz, 0.0f);

    // --- visibility via depth map
    int xc = (int)rintf(cx); xc = min(max(xc, 0), IMG_W - 1);
    int yc = (int)rintf(cy); yc = min(max(yc, 0), IMG_H - 1);
    const float d = __uint_as_float(g_depth[(size_t)b * HW + yc * IMG_W + xc]);
    // z <= inf is always true, so isinf(d) case is subsumed
    const float vw = (c3z <= d + 1e-3f) ? aw : 0.0f;

    if (lane == 0) {
        out_vw[gwarp] = vw;
        out_c3[3 * gwarp + 0] = c3x;
        out_c3[3 * gwarp + 1] = c3y;
        out_c3[3 * gwarp + 2] = c3z;
    }

    // --- bilinear sampling params (mirror reference formula exactly)
    const float gx = cx / (float)(IMG_W - 1) * 2.0f - 1.0f;
    const float gy = cy / (float)(IMG_H - 1) * 2.0f - 1.0f;
    const float px = (gx + 1.0f) * 0.5f * (float)(WF - 1);
    const float py = (gy + 1.0f) * 0.5f * (float)(HF - 1);
    const float x0f = floorf(px), y0f = floorf(py);
    const float wx = px - x0f, wy = py - y0f;
    const int x0 = (int)x0f, y0 = (int)y0f;
    const int x1 = x0 + 1,   y1 = y0 + 1;

    const float okx0 = (x0 >= 0 && x0 < WF) ? 1.0f : 0.0f;
    const float okx1 = (x1 >= 0 && x1 < WF) ? 1.0f : 0.0f;
    const float oky0 = (y0 >= 0 && y0 < HF) ? 1.0f : 0.0f;
    const float oky1 = (y1 >= 0 && y1 < HF) ? 1.0f : 0.0f;

    const float w00 = (1.0f - wx) * (1.0f - wy) * okx0 * oky0;
    const float w01 = wx          * (1.0f - wy) * okx1 * oky0;
    const float w10 = (1.0f - wx) * wy          * okx0 * oky1;
    const float w11 = wx          * wy          * okx1 * oky1;

    const int x0c = min(max(x0, 0), WF - 1);
    const int x1c = min(max(x1, 0), WF - 1);
    const int y0c = min(max(y0, 0), HF - 1);
    const int y1c = min(max(y1, 0), HF - 1);

    const float4* base = (const float4*)(g_fmT + (size_t)b * FHW * CC);
    const int c4 = CC / 4;  // 32 float4 per pixel, one per lane
    const float4 f00 = base[(size_t)(y0c * WF + x0c) * c4 + lane];
    const float4 f01 = base[(size_t)(y0c * WF + x1c) * c4 + lane];
    const float4 f10 = base[(size_t)(y1c * WF + x0c) * c4 + lane];
    const float4 f11 = base[(size_t)(y1c * WF + x1c) * c4 + lane];

    float4 o;
    o.x = w00 * f00.x + w01 * f01.x + w10 * f10.x + w11 * f11.x;
    o.y = w00 * f00.y + w01 * f01.y + w10 * f10.y + w11 * f11.y;
    o.z = w00 * f00.z + w01 * f01.z + w10 * f10.z + w11 * f11.z;
    o.w = w00 * f00.w + w01 * f01.w + w10 * f10.w + w11 * f11.w;

    ((float4*)out_feats)[(size_t)gwarp * c4 + lane] = o;
}

// ---------------------------------------------------------------------------
// Launch
// ---------------------------------------------------------------------------
extern "C" void kernel_launch(void* const* d_in, const int* in_sizes, int n_in,
                              void* d_out, int out_size) {
    const float* fm      = (const float*)d_in[0];
    const float* v2d     = (const float*)d_in[1];
    const float* v3d     = (const float*)d_in[2];
    const int*   parents = (const int*)d_in[3];
    const float* bary    = (const float*)d_in[4];
    (void)in_sizes; (void)n_in; (void)out_size;

    float* out_feats = (float*)d_out;                                   // B*N*C
    float* out_vw    = out_feats + (size_t)BB * NT * CC;                // B*N
    float* out_c3    = out_vw    + (size_t)BB * NT;                     // B*N*3

    // 1. transpose feature map into L2-resident scratch
    {
        dim3 grid(FHW / 32, CC / 32, BB);
        dim3 block(32, 8);
        transpose_k<<<grid, block>>>(fm);
    }
    // 2. depth init
    depth_init_k<<<(BB * HW + 255) / 256, 256>>>();
    // 3. depth scatter-min
    depth_scatter_k<<<(BB * NV + 255) / 256, 256>>>(v2d, v3d);
    // 4. main
    {
        const int warps = BB * NT;           // 800000
        const int blocks = (warps * 32 + 255) / 256;
        main_k<<<blocks, 256>>>(v2d, v3d, parents, bary,
                                out_feats, out_vw, out_c3);
    }
}

// round 2
// speedup vs baseline: 1.9041x; 1.9041x over previous
#include <cuda_runtime.h>
#include <cuda_bf16.h>
#include <cstdint>

// Problem constants (fixed by setup_inputs)
#define BB   4
#define CC   128
#define HF   128
#define WF   128
#define NV   10475
#define NT   200000
#define KB   20
#define IMG_H 512
#define IMG_W 512
#define HW   (IMG_H * IMG_W)
#define FHW  (HF * WF)

// Scratch: transposed feature map (B, Hf, Wf, C) and per-batch depth map.
__device__ float    g_fmT[(size_t)BB * FHW * CC];     // 33.5 MB
__device__ unsigned g_depth[(size_t)BB * HW];         // 4 MB

// ---------------------------------------------------------------------------
// Kernel 1: transpose (B,C,Hf*Wf) -> (B,Hf*Wf,C), tiled via smem
// ---------------------------------------------------------------------------
__global__ void transpose_k(const float* __restrict__ fm) {
    __shared__ float tile[32][33];
    const int b  = blockIdx.z;
    const int p0 = blockIdx.x * 32;   // spatial block
    const int c0 = blockIdx.y * 32;   // channel block
    const int tx = threadIdx.x;
    const int ty = threadIdx.y;       // block (32, 8)

    const float* src = fm + (size_t)b * CC * FHW;
#pragma unroll
    for (int i = 0; i < 32; i += 8)
        tile[ty + i][tx] = src[(size_t)(c0 + ty + i) * FHW + (p0 + tx)];
    __syncthreads();
    float* dst = g_fmT + (size_t)b * FHW * CC;
#pragma unroll
    for (int i = 0; i < 32; i += 8)
        dst[(size_t)(p0 + ty + i) * CC + (c0 + tx)] = tile[tx][ty + i];
}

// ---------------------------------------------------------------------------
// Kernel 2: init depth map to +inf
// ---------------------------------------------------------------------------
__global__ void depth_init_k() {
    int i = blockIdx.x * blockDim.x + threadIdx.x;
    if (i < BB * HW) g_depth[i] = 0x7f800000u;  // +inf bits
}

// ---------------------------------------------------------------------------
// Kernel 3: scatter-min z over rounded vertex pixels
// z in [1,5] (positive) -> uint-bit atomicMin == float min
// ---------------------------------------------------------------------------
__global__ void depth_scatter_k(const float* __restrict__ v2d,
                                const float* __restrict__ v3d) {
    int i = blockIdx.x * blockDim.x + threadIdx.x;   // i = b*NV + v
    if (i >= BB * NV) return;
    int b = i / NV;
    float x = v2d[2 * i];
    float y = v2d[2 * i + 1];
    int xi = (int)rintf(x);   // round-half-even, matches jnp.round
    int yi = (int)rintf(y);
    if (xi >= 0 && xi < IMG_W && yi >= 0 && yi < IMG_H) {
        float z = v3d[3 * i + 2];
        atomicMin(&g_depth[(size_t)b * HW + yi * IMG_W + xi], __float_as_uint(z));
    }
}

// ---------------------------------------------------------------------------
// Kernel 4: main — one warp per 32 points.
// Phase 1: each lane does the scalar pipeline for its own point (32x issue
//          amortization vs warp-per-point) and writes vw / centers3d.
// Phase 2: 32-iteration loop; broadcast lane k's params via shfl, then all
//          32 lanes do the coalesced 4-corner gather + blend + store.
// ---------------------------------------------------------------------------
__global__ void __launch_bounds__(256)
main_k(const float* __restrict__ v2d,
       const float* __restrict__ v3d,
       const int*   __restrict__ parents,
       const float* __restrict__ bary,
       float* __restrict__ out_feats,   // (B,N,C)
       float* __restrict__ out_vw,      // (B,N)
       float* __restrict__ out_c3)      // (B,N,3)
{
    const int warp_id = (blockIdx.x * blockDim.x + threadIdx.x) >> 5;
    const int lane    = threadIdx.x & 31;
    const int p       = warp_id * 32 + lane;     // this lane's point
    // BB*NT = 800000 divisible by 32; grid launched exactly -> p always valid
    const int b = p / NT;
    const int n = p - b * NT;

    // ---- Phase 1: per-lane scalar pipeline for point p ----
    const int p0 = __ldg(&parents[3 * n + 0]);
    const int p1 = __ldg(&parents[3 * n + 1]);
    const int p2 = __ldg(&parents[3 * n + 2]);
    const int r  = n % KB;
    const float w0 = __ldg(&bary[3 * r + 0]);
    const float w1 = __ldg(&bary[3 * r + 1]);
    const float w2 = __ldg(&bary[3 * r + 2]);

    const float* v2b = v2d + (size_t)b * NV * 2;
    const float* v3b = v3d + (size_t)b * NV * 3;

    const float2 q0 = *(const float2*)(v2b + 2 * p0);
    const float2 q1 = *(const float2*)(v2b + 2 * p1);
    const float2 q2 = *(const float2*)(v2b + 2 * p2);
    const float cx = w0 * q0.x + w1 * q1.x + w2 * q2.x;
    const float cy = w0 * q0.y + w1 * q1.y + w2 * q2.y;

    const float a0x = v3b[3 * p0], a0y = v3b[3 * p0 + 1], a0z = v3b[3 * p0 + 2];
    const float a1x = v3b[3 * p1], a1y = v3b[3 * p1 + 1], a1z = v3b[3 * p1 + 2];
    const float a2x = v3b[3 * p2], a2y = v3b[3 * p2 + 1], a2z = v3b[3 * p2 + 2];
    const float c3x = w0 * a0x + w1 * a1x + w2 * a2x;
    const float c3y = w0 * a0y + w1 * a1y + w2 * a2y;
    const float c3z = w0 * a0z + w1 * a1z + w2 * a2z;

    // face normal & angle weight
    const float e1x = a1x - a0x, e1y = a1y - a0y, e1z = a1z - a0z;
    const float e2x = a2x - a0x, e2y = a2y - a0y, e2z = a2z - a0z;
    float nx = e1y * e2z - e1z * e2y;
    float ny = e1z * e2x - e1x * e2z;
    float nz = e1x * e2y - e1y * e2x;
    const float nl = sqrtf(nx * nx + ny * ny + nz * nz) + 1e-8f;
    nx /= nl; ny /= nl; nz /= nl;
    const float vl = sqrtf(c3x * c3x + c3y * c3y + c3z * c3z) + 1e-8f;
    const float vx = -c3x / vl, vy = -c3y / vl, vz = -c3z / vl;
    const float aw = fmaxf(nx * vx + ny * vy + nz * vz, 0.0f);

    // visibility via depth map
    int xc = (int)rintf(cx); xc = min(max(xc, 0), IMG_W - 1);
    int yc = (int)rintf(cy); yc = min(max(yc, 0), IMG_H - 1);
    const float d = __uint_as_float(g_depth[(size_t)b * HW + yc * IMG_W + xc]);
    const float vw = (c3z <= d + 1e-3f) ? aw : 0.0f;   // z<=inf subsumes isinf

    out_vw[p] = vw;
    out_c3[3 * p + 0] = c3x;
    out_c3[3 * p + 1] = c3y;
    out_c3[3 * p + 2] = c3z;

    // bilinear sampling params (mirror reference formula exactly)
    const float gx = cx / (float)(IMG_W - 1) * 2.0f - 1.0f;
    const float gy = cy / (float)(IMG_H - 1) * 2.0f - 1.0f;
    const float px = (gx + 1.0f) * 0.5f * (float)(WF - 1);
    const float py = (gy + 1.0f) * 0.5f * (float)(HF - 1);
    const float x0f = floorf(px), y0f = floorf(py);
    const float wx = px - x0f, wy = py - y0f;
    const int x0 = (int)x0f, y0 = (int)y0f;
    const int x1 = x0 + 1,   y1 = y0 + 1;

    const float okx0 = (x0 >= 0 && x0 < WF) ? 1.0f : 0.0f;
    const float okx1 = (x1 >= 0 && x1 < WF) ? 1.0f : 0.0f;
    const float oky0 = (y0 >= 0 && y0 < HF) ? 1.0f : 0.0f;
    const float oky1 = (y1 >= 0 && y1 < HF) ? 1.0f : 0.0f;

    float w00 = (1.0f - wx) * (1.0f - wy) * okx0 * oky0;
    float w01 = wx          * (1.0f - wy) * okx1 * oky0;
    float w10 = (1.0f - wx) * wy          * okx0 * oky1;
    float w11 = wx          * wy          * okx1 * oky1;

    const int x0c = min(max(x0, 0), WF - 1);
    const int x1c = min(max(x1, 0), WF - 1);
    const int y0c = min(max(y0, 0), HF - 1);
    const int y1c = min(max(y1, 0), HF - 1);

    // corner base indices in float4 units, batch offset folded in
    const int bpix = b * FHW;
    int i00 = (bpix + y0c * WF + x0c) * (CC / 4);
    int i01 = (bpix + y0c * WF + x1c) * (CC / 4);
    int i10 = (bpix + y1c * WF + x0c) * (CC / 4);
    int i11 = (bpix + y1c * WF + x1c) * (CC / 4);

    // ---- Phase 2: loop over the warp's 32 points, broadcast + gather ----
    const float4* __restrict__ base4 = (const float4*)g_fmT;
    float4* __restrict__ outf = (float4*)out_feats;
    const size_t pbase = (size_t)warp_id * 32;

#pragma unroll 4
    for (int k = 0; k < 32; ++k) {
        const float a00 = __shfl_sync(0xffffffffu, w00, k);
        const float a01 = __shfl_sync(0xffffffffu, w01, k);
        const float a10 = __shfl_sync(0xffffffffu, w10, k);
        const float a11 = __shfl_sync(0xffffffffu, w11, k);
        const int   j00 = __shfl_sync(0xffffffffu, i00, k);
        const int   j01 = __shfl_sync(0xffffffffu, i01, k);
        const int   j10 = __shfl_sync(0xffffffffu, i10, k);
        const int   j11 = __shfl_sync(0xffffffffu, i11, k);

        const float4 f00 = base4[(size_t)j00 + lane];
        const float4 f01 = base4[(size_t)j01 + lane];
        const float4 f10 = base4[(size_t)j10 + lane];
        const float4 f11 = base4[(size_t)j11 + lane];

        float4 o;
        o.x = a00 * f00.x + a01 * f01.x + a10 * f10.x + a11 * f11.x;
        o.y = a00 * f00.y + a01 * f01.y + a10 * f10.y + a11 * f11.y;
        o.z = a00 * f00.z + a01 * f01.z + a10 * f10.z + a11 * f11.z;
        o.w = a00 * f00.w + a01 * f01.w + a10 * f10.w + a11 * f11.w;

        outf[(pbase + k) * (CC / 4) + lane] = o;
    }
}

// ---------------------------------------------------------------------------
// Launch
// ---------------------------------------------------------------------------
extern "C" void kernel_launch(void* const* d_in, const int* in_sizes, int n_in,
                              void* d_out, int out_size) {
    const float* fm      = (const float*)d_in[0];
    const float* v2d     = (const float*)d_in[1];
    const float* v3d     = (const float*)d_in[2];
    const int*   parents = (const int*)d_in[3];
    const float* bary    = (const float*)d_in[4];
    (void)in_sizes; (void)n_in; (void)out_size;

    float* out_feats = (float*)d_out;                                   // B*N*C
    float* out_vw    = out_feats + (size_t)BB * NT * CC;                // B*N
    float* out_c3    = out_vw    + (size_t)BB * NT;                     // B*N*3

    // 1. transpose feature map into L2-resident scratch
    {
        dim3 grid(FHW / 32, CC / 32, BB);
        dim3 block(32, 8);
        transpose_k<<<grid, block>>>(fm);
    }
    // 2. depth init
    depth_init_k<<<(BB * HW + 255) / 256, 256>>>();
    // 3. depth scatter-min
    depth_scatter_k<<<(BB * NV + 255) / 256, 256>>>(v2d, v3d);
    // 4. main: one warp per 32 points
    {
        const int total_threads = BB * NT;   // 800000 threads = 25000 warps
        const int blocks = total_threads / 256;  // 3125
        main_k<<<blocks, 256>>>(v2d, v3d, parents, bary,
                                out_feats, out_vw, out_c3);
    }
}

// round 3
// speedup vs baseline: 1.9357x; 1.0166x over previous
#include <cuda_runtime.h>
#include <cuda_fp16.h>
#include <cstdint>

// Problem constants (fixed by setup_inputs)
#define BB   4
#define CC   128
#define HF   128
#define WF   128
#define NV   10475
#define NT   200000
#define KB   20
#define IMG_H 512
#define IMG_W 512
#define HW   (IMG_H * IMG_W)
#define FHW  (HF * WF)

// Scratch: transposed fp16 feature map (B, Hf*Wf, C) and per-batch depth map.
__device__ __half   g_fmH[(size_t)BB * FHW * CC];     // 16.8 MB (L2-resident)
__device__ unsigned g_depth[(size_t)BB * HW];         // 4 MB

// ---------------------------------------------------------------------------
// Kernel 1: transpose (B,C,Hf*Wf) f32 -> (B,Hf*Wf,C) fp16, tiled via smem
// ---------------------------------------------------------------------------
__global__ void transpose_k(const float* __restrict__ fm) {
    __shared__ float tile[32][33];
    const int b  = blockIdx.z;
    const int p0 = blockIdx.x * 32;   // spatial block
    const int c0 = blockIdx.y * 32;   // channel block
    const int tx = threadIdx.x;
    const int ty = threadIdx.y;       // block (32, 8)

    const float* src = fm + (size_t)b * CC * FHW;
#pragma unroll
    for (int i = 0; i < 32; i += 8)
        tile[ty + i][tx] = src[(size_t)(c0 + ty + i) * FHW + (p0 + tx)];
    __syncthreads();
    __half* dst = g_fmH + (size_t)b * FHW * CC;
#pragma unroll
    for (int i = 0; i < 32; i += 8)
        dst[(size_t)(p0 + ty + i) * CC + (c0 + tx)] =
            __float2half_rn(tile[tx][ty + i]);
}

// ---------------------------------------------------------------------------
// Kernel 2: init depth map to +inf
// ---------------------------------------------------------------------------
__global__ void depth_init_k() {
    int i = blockIdx.x * blockDim.x + threadIdx.x;
    if (i < BB * HW) g_depth[i] = 0x7f800000u;  // +inf bits
}

// ---------------------------------------------------------------------------
// Kernel 3: scatter-min z over rounded vertex pixels
// ---------------------------------------------------------------------------
__global__ void depth_scatter_k(const float* __restrict__ v2d,
                                const float* __restrict__ v3d) {
    int i = blockIdx.x * blockDim.x + threadIdx.x;   // i = b*NV + v
    if (i >= BB * NV) return;
    int b = i / NV;
    float x = v2d[2 * i];
    float y = v2d[2 * i + 1];
    int xi = (int)rintf(x);   // round-half-even, matches jnp.round
    int yi = (int)rintf(y);
    if (xi >= 0 && xi < IMG_W && yi >= 0 && yi < IMG_H) {
        float z = v3d[3 * i + 2];
        atomicMin(&g_depth[(size_t)b * HW + yi * IMG_W + xi], __float_as_uint(z));
    }
}

// ---------------------------------------------------------------------------
// Kernel 4: main — one warp per 32 points.
// Phase 1: per-lane scalar pipeline (32x issue amortization).
// Phase 2: per point, half-warp-split corner gather:
//   lanes 0-15 read pixel (row, x0), lanes 16-31 read pixel (row, x1),
//   2 rows -> 2 LDG.128/point; shfl_xor(16) merges the x-corners.
// ---------------------------------------------------------------------------
__global__ void __launch_bounds__(256)
main_k(const float* __restrict__ v2d,
       const float* __restrict__ v3d,
       const int*   __restrict__ parents,
       const float* __restrict__ bary,
       float* __restrict__ out_feats,   // (B,N,C)
       float* __restrict__ out_vw,      // (B,N)
       float* __restrict__ out_c3)      // (B,N,3)
{
    const int warp_id = (blockIdx.x * blockDim.x + threadIdx.x) >> 5;
    const int lane    = threadIdx.x & 31;
    const int p       = warp_id * 32 + lane;     // this lane's point
    const int b = p / NT;
    const int n = p - b * NT;

    // ---- Phase 1: per-lane scalar pipeline for point p ----
    const int p0 = __ldg(&parents[3 * n + 0]);
    const int p1 = __ldg(&parents[3 * n + 1]);
    const int p2 = __ldg(&parents[3 * n + 2]);
    const int r  = n % KB;
    const float w0 = __ldg(&bary[3 * r + 0]);
    const float w1 = __ldg(&bary[3 * r + 1]);
    const float w2 = __ldg(&bary[3 * r + 2]);

    const float* v2b = v2d + (size_t)b * NV * 2;
    const float* v3b = v3d + (size_t)b * NV * 3;

    const float2 q0 = *(const float2*)(v2b + 2 * p0);
    const float2 q1 = *(const float2*)(v2b + 2 * p1);
    const float2 q2 = *(const float2*)(v2b + 2 * p2);
    const float cx = w0 * q0.x + w1 * q1.x + w2 * q2.x;
    const float cy = w0 * q0.y + w1 * q1.y + w2 * q2.y;

    const float a0x = v3b[3 * p0], a0y = v3b[3 * p0 + 1], a0z = v3b[3 * p0 + 2];
    const float a1x = v3b[3 * p1], a1y = v3b[3 * p1 + 1], a1z = v3b[3 * p1 + 2];
    const float a2x = v3b[3 * p2], a2y = v3b[3 * p2 + 1], a2z = v3b[3 * p2 + 2];
    const float c3x = w0 * a0x + w1 * a1x + w2 * a2x;
    const float c3y = w0 * a0y + w1 * a1y + w2 * a2y;
    const float c3z = w0 * a0z + w1 * a1z + w2 * a2z;

    // face normal & angle weight
    const float e1x = a1x - a0x, e1y = a1y - a0y, e1z = a1z - a0z;
    const float e2x = a2x - a0x, e2y = a2y - a0y, e2z = a2z - a0z;
    float nx = e1y * e2z - e1z * e2y;
    float ny = e1z * e2x - e1x * e2z;
    float nz = e1x * e2y - e1y * e2x;
    const float nl = sqrtf(nx * nx + ny * ny + nz * nz) + 1e-8f;
    nx /= nl; ny /= nl; nz /= nl;
    const float vl = sqrtf(c3x * c3x + c3y * c3y + c3z * c3z) + 1e-8f;
    const float vx = -c3x / vl, vy = -c3y / vl, vz = -c3z / vl;
    const float aw = fmaxf(nx * vx + ny * vy + nz * vz, 0.0f);

    // visibility via depth map
    int xc = (int)rintf(cx); xc = min(max(xc, 0), IMG_W - 1);
    int yc = (int)rintf(cy); yc = min(max(yc, 0), IMG_H - 1);
    const float d = __uint_as_float(g_depth[(size_t)b * HW + yc * IMG_W + xc]);
    const float vw = (c3z <= d + 1e-3f) ? aw : 0.0f;   // z<=inf subsumes isinf

    out_vw[p] = vw;
    out_c3[3 * p + 0] = c3x;
    out_c3[3 * p + 1] = c3y;
    out_c3[3 * p + 2] = c3z;

    // bilinear sampling params (mirror reference formula exactly)
    const float gx = cx / (float)(IMG_W - 1) * 2.0f - 1.0f;
    const float gy = cy / (float)(IMG_H - 1) * 2.0f - 1.0f;
    const float px = (gx + 1.0f) * 0.5f * (float)(WF - 1);
    const float py = (gy + 1.0f) * 0.5f * (float)(HF - 1);
    const float x0f = floorf(px), y0f = floorf(py);
    const float wx = px - x0f, wy = py - y0f;
    const int x0 = (int)x0f, y0 = (int)y0f;
    const int x1 = x0 + 1,   y1 = y0 + 1;

    const float okx0 = (x0 >= 0 && x0 < WF) ? 1.0f : 0.0f;
    const float okx1 = (x1 >= 0 && x1 < WF) ? 1.0f : 0.0f;
    const float oky0 = (y0 >= 0 && y0 < HF) ? 1.0f : 0.0f;
    const float oky1 = (y1 >= 0 && y1 < HF) ? 1.0f : 0.0f;

    float w00 = (1.0f - wx) * (1.0f - wy) * okx0 * oky0;
    float w01 = wx          * (1.0f - wy) * okx1 * oky0;
    float w10 = (1.0f - wx) * wy          * okx0 * oky1;
    float w11 = wx          * wy          * okx1 * oky1;

    const int x0c = min(max(x0, 0), WF - 1);
    const int x1c = min(max(x1, 0), WF - 1);
    const int y0c = min(max(y0, 0), HF - 1);
    const int y1c = min(max(y1, 0), HF - 1);

    // corner pixel indices, batch offset folded in
    const int bpix = b * FHW;
    int i00 = bpix + y0c * WF + x0c;
    int i01 = bpix + y0c * WF + x1c;
    int i10 = bpix + y1c * WF + x0c;
    int i11 = bpix + y1c * WF + x1c;

    // ---- Phase 2: loop over the warp's 32 points ----
    const bool lo  = (lane < 16);
    const int  sub = lane & 15;                 // channel group: 8 ch per lane
    float4* __restrict__ outf = (float4*)out_feats;
    const size_t pbase = (size_t)warp_id * 32;

#pragma unroll 4
    for (int k = 0; k < 32; ++k) {
        const int   j00 = __shfl_sync(0xffffffffu, i00, k);
        const int   j01 = __shfl_sync(0xffffffffu, i01, k);
        const int   j10 = __shfl_sync(0xffffffffu, i10, k);
        const int   j11 = __shfl_sync(0xffffffffu, i11, k);
        const float a00 = __shfl_sync(0xffffffffu, w00, k);
        const float a01 = __shfl_sync(0xffffffffu, w01, k);
        const float a10 = __shfl_sync(0xffffffffu, w10, k);
        const float a11 = __shfl_sync(0xffffffffu, w11, k);

        // half-warp split: lo lanes take x0 corner, hi lanes take x1 corner
        const int   pixR0 = lo ? j00 : j01;
        const int   pixR1 = lo ? j10 : j11;
        const float wR0   = lo ? a00 : a01;
        const float wR1   = lo ? a10 : a11;

        const uint4 r0 = *(const uint4*)(g_fmH + (size_t)pixR0 * CC + sub * 8);
        const uint4 r1 = *(const uint4*)(g_fmH + (size_t)pixR1 * CC + sub * 8);

        // blend: acc = wR0 * f_row0 + wR1 * f_row1  (8 channels per lane)
        float acc[8];
        {
            const __half2* h0 = (const __half2*)&r0;
            const __half2* h1 = (const __half2*)&r1;
#pragma unroll
            for (int q = 0; q < 4; ++q) {
                const float2 f0 = __half22float2(h0[q]);
                const float2 f1 = __half22float2(h1[q]);
                acc[2 * q + 0] = wR0 * f0.x + wR1 * f1.x;
                acc[2 * q + 1] = wR0 * f0.y + wR1 * f1.y;
            }
        }
        // merge x0/x1 halves: lanes l and l+16 hold the same channels
#pragma unroll
        for (int q = 0; q < 8; ++q)
            acc[q] += __shfl_xor_sync(0xffffffffu, acc[q], 16);

        // store: lo lane -> channels sub*8..+3, hi lane -> sub*8+4..+7
        float4 o = lo ? make_float4(acc[0], acc[1], acc[2], acc[3])
                      : make_float4(acc[4], acc[5], acc[6], acc[7]);
        const int ch4 = sub * 2 + (lo ? 0 : 1);
        outf[(pbase + k) * (CC / 4) + ch4] = o;
    }
}

// ---------------------------------------------------------------------------
// Launch
// ---------------------------------------------------------------------------
extern "C" void kernel_launch(void* const* d_in, const int* in_sizes, int n_in,
                              void* d_out, int out_size) {
    const float* fm      = (const float*)d_in[0];
    const float* v2d     = (const float*)d_in[1];
    const float* v3d     = (const float*)d_in[2];
    const int*   parents = (const int*)d_in[3];
    const float* bary    = (const float*)d_in[4];
    (void)in_sizes; (void)n_in; (void)out_size;

    float* out_feats = (float*)d_out;                                   // B*N*C
    float* out_vw    = out_feats + (size_t)BB * NT * CC;                // B*N
    float* out_c3    = out_vw    + (size_t)BB * NT;                     // B*N*3

    // 1. transpose + fp16 convert feature map into L2-resident scratch
    {
        dim3 grid(FHW / 32, CC / 32, BB);
        dim3 block(32, 8);
        transpose_k<<<grid, block>>>(fm);
    }
    // 2. depth init
    depth_init_k<<<(BB * HW + 255) / 256, 256>>>();
    // 3. depth scatter-min
    depth_scatter_k<<<(BB * NV + 255) / 256, 256>>>(v2d, v3d);
    // 4. main: one warp per 32 points
    {
        const int total_threads = BB * NT;       // 800000 = 25000 warps
        const int blocks = total_threads / 256;  // 3125
        main_k<<<blocks, 256>>>(v2d, v3d, parents, bary,
                                out_feats, out_vw, out_c3);
    }
}

// round 4
// speedup vs baseline: 1.9635x; 1.0144x over previous
#include <cuda_runtime.h>
#include <cuda_fp16.h>
#include <cstdint>

// Problem constants (fixed by setup_inputs)
#define BB   4
#define CC   128
#define HF   128
#define WF   128
#define NV   10475
#define NT   200000
#define KB   20
#define IMG_H 512
#define IMG_W 512
#define HW   (IMG_H * IMG_W)
#define FHW  (HF * WF)

// Scratch
__device__ __half   g_fmH[(size_t)BB * FHW * CC];     // 16.8 MB transposed fp16 features
__device__ unsigned g_depth[(size_t)BB * HW];         // 4 MB depth map
__device__ float4   g_vp[(size_t)BB * NV];            // packed (x2d,y2d,x3d,y3d)
__device__ float    g_vz[(size_t)BB * NV];            // z3d

// ---------------------------------------------------------------------------
// Kernel 0: pack vertex records for line-efficient gathers
// ---------------------------------------------------------------------------
__global__ void pack_k(const float* __restrict__ v2d,
                       const float* __restrict__ v3d) {
    int i = blockIdx.x * blockDim.x + threadIdx.x;   // i = b*NV + v
    if (i >= BB * NV) return;
    float4 r;
    r.x = v2d[2 * i];
    r.y = v2d[2 * i + 1];
    r.z = v3d[3 * i];
    r.w = v3d[3 * i + 1];
    g_vp[i] = r;
    g_vz[i] = v3d[3 * i + 2];
}

// ---------------------------------------------------------------------------
// Kernel 1: transpose (B,C,Hf*Wf) f32 -> (B,Hf*Wf,C) fp16, tiled via smem
// ---------------------------------------------------------------------------
__global__ void transpose_k(const float* __restrict__ fm) {
    __shared__ float tile[32][33];
    const int b  = blockIdx.z;
    const int p0 = blockIdx.x * 32;   // spatial block
    const int c0 = blockIdx.y * 32;   // channel block
    const int tx = threadIdx.x;
    const int ty = threadIdx.y;       // block (32, 8)

    const float* src = fm + (size_t)b * CC * FHW;
#pragma unroll
    for (int i = 0; i < 32; i += 8)
        tile[ty + i][tx] = src[(size_t)(c0 + ty + i) * FHW + (p0 + tx)];
    __syncthreads();
    __half* dst = g_fmH + (size_t)b * FHW * CC;
#pragma unroll
    for (int i = 0; i < 32; i += 8)
        dst[(size_t)(p0 + ty + i) * CC + (c0 + tx)] =
            __float2half_rn(tile[tx][ty + i]);
}

// ---------------------------------------------------------------------------
// Kernel 2: init depth map to +inf
// ---------------------------------------------------------------------------
__global__ void depth_init_k() {
    int i = blockIdx.x * blockDim.x + threadIdx.x;
    if (i < BB * HW) g_depth[i] = 0x7f800000u;  // +inf bits
}

// ---------------------------------------------------------------------------
// Kernel 3: scatter-min z over rounded vertex pixels
// ---------------------------------------------------------------------------
__global__ void depth_scatter_k(const float* __restrict__ v2d,
                                const float* __restrict__ v3d) {
    int i = blockIdx.x * blockDim.x + threadIdx.x;   // i = b*NV + v
    if (i >= BB * NV) return;
    int b = i / NV;
    float x = v2d[2 * i];
    float y = v2d[2 * i + 1];
    int xi = (int)rintf(x);   // round-half-even, matches jnp.round
    int yi = (int)rintf(y);
    if (xi >= 0 && xi < IMG_W && yi >= 0 && yi < IMG_H) {
        float z = v3d[3 * i + 2];
        atomicMin(&g_depth[(size_t)b * HW + yi * IMG_W + xi], __float_as_uint(z));
    }
}

// ---------------------------------------------------------------------------
// Kernel 4: main — one warp per 32 points.
// Phase 1: per-lane scalar pipeline with packed-vertex gathers.
// Phase 2: half-warp-split corner gather at the wavefront floor.
// ---------------------------------------------------------------------------
__global__ void __launch_bounds__(256)
main_k(const int*   __restrict__ parents,
       const float* __restrict__ bary,
       float* __restrict__ out_feats,   // (B,N,C)
       float* __restrict__ out_vw,      // (B,N)
       float* __restrict__ out_c3)      // (B,N,3)
{
    const int warp_id = (blockIdx.x * blockDim.x + threadIdx.x) >> 5;
    const int lane    = threadIdx.x & 31;
    const int p       = warp_id * 32 + lane;     // this lane's point
    const int b = p / NT;
    const int n = p - b * NT;

    // ---- Phase 1: per-lane scalar pipeline for point p ----
    const int p0 = __ldg(&parents[3 * n + 0]);
    const int p1 = __ldg(&parents[3 * n + 1]);
    const int p2 = __ldg(&parents[3 * n + 2]);
    const int r  = n % KB;
    const float w0 = __ldg(&bary[3 * r + 0]);
    const float w1 = __ldg(&bary[3 * r + 1]);
    const float w2 = __ldg(&bary[3 * r + 2]);

    const int bnv = b * NV;
    const float4 V0 = __ldg(&g_vp[bnv + p0]);
    const float4 V1 = __ldg(&g_vp[bnv + p1]);
    const float4 V2 = __ldg(&g_vp[bnv + p2]);
    const float a0z = __ldg(&g_vz[bnv + p0]);
    const float a1z = __ldg(&g_vz[bnv + p1]);
    const float a2z = __ldg(&g_vz[bnv + p2]);

    const float cx = w0 * V0.x + w1 * V1.x + w2 * V2.x;
    const float cy = w0 * V0.y + w1 * V1.y + w2 * V2.y;

    const float a0x = V0.z, a0y = V0.w;
    const float a1x = V1.z, a1y = V1.w;
    const float a2x = V2.z, a2y = V2.w;
    const float c3x = w0 * a0x + w1 * a1x + w2 * a2x;
    const float c3y = w0 * a0y + w1 * a1y + w2 * a2y;
    const float c3z = w0 * a0z + w1 * a1z + w2 * a2z;

    // face normal & angle weight
    const float e1x = a1x - a0x, e1y = a1y - a0y, e1z = a1z - a0z;
    const float e2x = a2x - a0x, e2y = a2y - a0y, e2z = a2z - a0z;
    float nx = e1y * e2z - e1z * e2y;
    float ny = e1z * e2x - e1x * e2z;
    float nz = e1x * e2y - e1y * e2x;
    const float nl = sqrtf(nx * nx + ny * ny + nz * nz) + 1e-8f;
    nx /= nl; ny /= nl; nz /= nl;
    const float vl = sqrtf(c3x * c3x + c3y * c3y + c3z * c3z) + 1e-8f;
    const float vx = -c3x / vl, vy = -c3y / vl, vz = -c3z / vl;
    const float aw = fmaxf(nx * vx + ny * vy + nz * vz, 0.0f);

    // visibility via depth map
    int xc = (int)rintf(cx); xc = min(max(xc, 0), IMG_W - 1);
    int yc = (int)rintf(cy); yc = min(max(yc, 0), IMG_H - 1);
    const float d = __uint_as_float(g_depth[(size_t)b * HW + yc * IMG_W + xc]);
    const float vw = (c3z <= d + 1e-3f) ? aw : 0.0f;   // z<=inf subsumes isinf

    out_vw[p] = vw;
    out_c3[3 * p + 0] = c3x;
    out_c3[3 * p + 1] = c3y;
    out_c3[3 * p + 2] = c3z;

    // bilinear sampling params (mirror reference formula exactly)
    const float gx = cx / (float)(IMG_W - 1) * 2.0f - 1.0f;
    const float gy = cy / (float)(IMG_H - 1) * 2.0f - 1.0f;
    const float px = (gx + 1.0f) * 0.5f * (float)(WF - 1);
    const float py = (gy + 1.0f) * 0.5f * (float)(HF - 1);
    const float x0f = floorf(px), y0f = floorf(py);
    const float wx = px - x0f, wy = py - y0f;
    const int x0 = (int)x0f, y0 = (int)y0f;
    const int x1 = x0 + 1,   y1 = y0 + 1;

    const float okx0 = (x0 >= 0 && x0 < WF) ? 1.0f : 0.0f;
    const float okx1 = (x1 >= 0 && x1 < WF) ? 1.0f : 0.0f;
    const float oky0 = (y0 >= 0 && y0 < HF) ? 1.0f : 0.0f;
    const float oky1 = (y1 >= 0 && y1 < HF) ? 1.0f : 0.0f;

    float w00 = (1.0f - wx) * (1.0f - wy) * okx0 * oky0;
    float w01 = wx          * (1.0f - wy) * okx1 * oky0;
    float w10 = (1.0f - wx) * wy          * okx0 * oky1;
    float w11 = wx          * wy          * okx1 * oky1;

    const int x0c = min(max(x0, 0), WF - 1);
    const int x1c = min(max(x1, 0), WF - 1);
    const int y0c = min(max(y0, 0), HF - 1);
    const int y1c = min(max(y1, 0), HF - 1);

    // corner pixel indices, batch offset folded in
    const int bpix = b * FHW;
    int i00 = bpix + y0c * WF + x0c;
    int i01 = bpix + y0c * WF + x1c;
    int i10 = bpix + y1c * WF + x0c;
    int i11 = bpix + y1c * WF + x1c;

    // ---- Phase 2: loop over the warp's 32 points ----
    const bool lo  = (lane < 16);
    const int  sub = lane & 15;                 // channel group: 8 ch per lane
    float4* __restrict__ outf = (float4*)out_feats;
    const size_t pbase = (size_t)warp_id * 32;

#pragma unroll 4
    for (int k = 0; k < 32; ++k) {
        const int   j00 = __shfl_sync(0xffffffffu, i00, k);
        const int   j01 = __shfl_sync(0xffffffffu, i01, k);
        const int   j10 = __shfl_sync(0xffffffffu, i10, k);
        const int   j11 = __shfl_sync(0xffffffffu, i11, k);
        const float a00 = __shfl_sync(0xffffffffu, w00, k);
        const float a01 = __shfl_sync(0xffffffffu, w01, k);
        const float a10 = __shfl_sync(0xffffffffu, w10, k);
        const float a11 = __shfl_sync(0xffffffffu, w11, k);

        // half-warp split: lo lanes take x0 corner, hi lanes take x1 corner
        const int   pixR0 = lo ? j00 : j01;
        const int   pixR1 = lo ? j10 : j11;
        const float wR0   = lo ? a00 : a01;
        const float wR1   = lo ? a10 : a11;

        const uint4 r0 = *(const uint4*)(g_fmH + (size_t)pixR0 * CC + sub * 8);
        const uint4 r1 = *(const uint4*)(g_fmH + (size_t)pixR1 * CC + sub * 8);

        // blend: acc = wR0 * f_row0 + wR1 * f_row1  (8 channels per lane)
        float acc[8];
        {
            const __half2* h0 = (const __half2*)&r0;
            const __half2* h1 = (const __half2*)&r1;
#pragma unroll
            for (int q = 0; q < 4; ++q) {
                const float2 f0 = __half22float2(h0[q]);
                const float2 f1 = __half22float2(h1[q]);
                acc[2 * q + 0] = wR0 * f0.x + wR1 * f1.x;
                acc[2 * q + 1] = wR0 * f0.y + wR1 * f1.y;
            }
        }
        // merge x0/x1 halves: lanes l and l+16 hold the same channels
#pragma unroll
        for (int q = 0; q < 8; ++q)
            acc[q] += __shfl_xor_sync(0xffffffffu, acc[q], 16);

        // store: lo lane -> channels sub*8..+3, hi lane -> sub*8+4..+7
        float4 o = lo ? make_float4(acc[0], acc[1], acc[2], acc[3])
                      : make_float4(acc[4], acc[5], acc[6], acc[7]);
        const int ch4 = sub * 2 + (lo ? 0 : 1);
        outf[(pbase + k) * (CC / 4) + ch4] = o;
    }
}

// ---------------------------------------------------------------------------
// Launch
// ---------------------------------------------------------------------------
extern "C" void kernel_launch(void* const* d_in, const int* in_sizes, int n_in,
                              void* d_out, int out_size) {
    const float* fm      = (const float*)d_in[0];
    const float* v2d     = (const float*)d_in[1];
    const float* v3d     = (const float*)d_in[2];
    const int*   parents = (const int*)d_in[3];
    const float* bary    = (const float*)d_in[4];
    (void)in_sizes; (void)n_in; (void)out_size;

    float* out_feats = (float*)d_out;                                   // B*N*C
    float* out_vw    = out_feats + (size_t)BB * NT * CC;                // B*N
    float* out_c3    = out_vw    + (size_t)BB * NT;                     // B*N*3

    // 0. pack vertex records
    pack_k<<<(BB * NV + 255) / 256, 256>>>(v2d, v3d);
    // 1. transpose + fp16 convert feature map into L2-resident scratch
    {
        dim3 grid(FHW / 32, CC / 32, BB);
        dim3 block(32, 8);
        transpose_k<<<grid, block>>>(fm);
    }
    // 2. depth init
    depth_init_k<<<(BB * HW + 255) / 256, 256>>>();
    // 3. depth scatter-min
    depth_scatter_k<<<(BB * NV + 255) / 256, 256>>>(v2d, v3d);
    // 4. main: one warp per 32 points
    {
        const int total_threads = BB * NT;       // 800000 = 25000 warps
        const int blocks = total_threads / 256;  // 3125
        main_k<<<blocks, 256>>>(parents, bary, out_feats, out_vw, out_c3);
    }
}

// round 5
// speedup vs baseline: 2.3392x; 1.1913x over previous
#include <cuda_runtime.h>
#include <cuda_fp16.h>
#include <cstdint>

// Problem constants (fixed by setup_inputs)
#define BB   4
#define CC   128
#define HF   128
#define WF   128
#define NV   10475
#define NT   200000
#define KB   20
#define IMG_H 512
#define IMG_W 512
#define HW   (IMG_H * IMG_W)
#define FHW  (HF * WF)

// Scratch
__device__ __half   g_fmH[(size_t)BB * FHW * CC];     // 16.8 MB transposed fp16 features
__device__ unsigned g_depth[(size_t)BB * HW];         // 4 MB depth map
__device__ float4   g_vp[(size_t)BB * NV];            // packed (x2d,y2d,x3d,y3d)
__device__ float    g_vz[(size_t)BB * NV];            // z3d

// ---------------------------------------------------------------------------
// Kernel 0: pack vertex records for line-efficient gathers
// ---------------------------------------------------------------------------
__global__ void pack_k(const float* __restrict__ v2d,
                       const float* __restrict__ v3d) {
    int i = blockIdx.x * blockDim.x + threadIdx.x;   // i = b*NV + v
    if (i >= BB * NV) return;
    float4 r;
    r.x = v2d[2 * i];
    r.y = v2d[2 * i + 1];
    r.z = v3d[3 * i];
    r.w = v3d[3 * i + 1];
    g_vp[i] = r;
    g_vz[i] = v3d[3 * i + 2];
}

// ---------------------------------------------------------------------------
// Kernel 1: transpose (B,C,Hf*Wf) f32 -> (B,Hf*Wf,C) fp16, tiled via smem
// ---------------------------------------------------------------------------
__global__ void transpose_k(const float* __restrict__ fm) {
    __shared__ float tile[32][33];
    const int b  = blockIdx.z;
    const int p0 = blockIdx.x * 32;   // spatial block
    const int c0 = blockIdx.y * 32;   // channel block
    const int tx = threadIdx.x;
    const int ty = threadIdx.y;       // block (32, 8)

    const float* src = fm + (size_t)b * CC * FHW;
#pragma unroll
    for (int i = 0; i < 32; i += 8)
        tile[ty + i][tx] = src[(size_t)(c0 + ty + i) * FHW + (p0 + tx)];
    __syncthreads();
    __half* dst = g_fmH + (size_t)b * FHW * CC;
#pragma unroll
    for (int i = 0; i < 32; i += 8)
        dst[(size_t)(p0 + ty + i) * CC + (c0 + tx)] =
            __float2half_rn(tile[tx][ty + i]);
}

// ---------------------------------------------------------------------------
// Kernel 2: init depth map to +inf
// ---------------------------------------------------------------------------
__global__ void depth_init_k() {
    int i = blockIdx.x * blockDim.x + threadIdx.x;
    if (i < BB * HW) g_depth[i] = 0x7f800000u;  // +inf bits
}

// ---------------------------------------------------------------------------
// Kernel 3: scatter-min z over rounded vertex pixels
// ---------------------------------------------------------------------------
__global__ void depth_scatter_k(const float* __restrict__ v2d,
                                const float* __restrict__ v3d) {
    int i = blockIdx.x * blockDim.x + threadIdx.x;   // i = b*NV + v
    if (i >= BB * NV) return;
    int b = i / NV;
    float x = v2d[2 * i];
    float y = v2d[2 * i + 1];
    int xi = (int)rintf(x);   // round-half-even, matches jnp.round
    int yi = (int)rintf(y);
    if (xi >= 0 && xi < IMG_W && yi >= 0 && yi < IMG_H) {
        float z = v3d[3 * i + 2];
        atomicMin(&g_depth[(size_t)b * HW + yi * IMG_W + xi], __float_as_uint(z));
    }
}

// ---------------------------------------------------------------------------
// Kernel 4: main — one warp per 32 points.
// Phase 1: per-lane scalar pipeline; params staged to smem (no shuffles).
// Phase 2: per point, each lane owns 4 channels and loads all 4 corners
//   itself (uint2 = 4 fp16 per corner) — zero cross-lane communication.
// ---------------------------------------------------------------------------
__global__ void __launch_bounds__(256)
main_k(const int*   __restrict__ parents,
       const float* __restrict__ bary,
       float* __restrict__ out_feats,   // (B,N,C)
       float* __restrict__ out_vw,      // (B,N)
       float* __restrict__ out_c3)      // (B,N,3)
{
    __shared__ int4   s_idx[8][32];   // per-warp per-point corner offsets (half-elem units)
    __shared__ float4 s_w[8][32];     // per-warp per-point bilinear weights

    const int warp_id = (blockIdx.x * blockDim.x + threadIdx.x) >> 5;
    const int wl      = (threadIdx.x >> 5);      // warp within block
    const int lane    = threadIdx.x & 31;
    const int p       = warp_id * 32 + lane;     // this lane's point
    const int b = p / NT;
    const int n = p - b * NT;

    // ---- Phase 1: per-lane scalar pipeline for point p ----
    const int p0 = __ldg(&parents[3 * n + 0]);
    const int p1 = __ldg(&parents[3 * n + 1]);
    const int p2 = __ldg(&parents[3 * n + 2]);
    const int r  = n % KB;
    const float w0 = __ldg(&bary[3 * r + 0]);
    const float w1 = __ldg(&bary[3 * r + 1]);
    const float w2 = __ldg(&bary[3 * r + 2]);

    const int bnv = b * NV;
    const float4 V0 = __ldg(&g_vp[bnv + p0]);
    const float4 V1 = __ldg(&g_vp[bnv + p1]);
    const float4 V2 = __ldg(&g_vp[bnv + p2]);
    const float a0z = __ldg(&g_vz[bnv + p0]);
    const float a1z = __ldg(&g_vz[bnv + p1]);
    const float a2z = __ldg(&g_vz[bnv + p2]);

    const float cx = w0 * V0.x + w1 * V1.x + w2 * V2.x;
    const float cy = w0 * V0.y + w1 * V1.y + w2 * V2.y;

    const float a0x = V0.z, a0y = V0.w;
    const float a1x = V1.z, a1y = V1.w;
    const float a2x = V2.z, a2y = V2.w;
    const float c3x = w0 * a0x + w1 * a1x + w2 * a2x;
    const float c3y = w0 * a0y + w1 * a1y + w2 * a2y;
    const float c3z = w0 * a0z + w1 * a1z + w2 * a2z;

    // face normal & angle weight
    const float e1x = a1x - a0x, e1y = a1y - a0y, e1z = a1z - a0z;
    const float e2x = a2x - a0x, e2y = a2y - a0y, e2z = a2z - a0z;
    float nx = e1y * e2z - e1z * e2y;
    float ny = e1z * e2x - e1x * e2z;
    float nz = e1x * e2y - e1y * e2x;
    const float nl = sqrtf(nx * nx + ny * ny + nz * nz) + 1e-8f;
    nx /= nl; ny /= nl; nz /= nl;
    const float vl = sqrtf(c3x * c3x + c3y * c3y + c3z * c3z) + 1e-8f;
    const float vx = -c3x / vl, vy = -c3y / vl, vz = -c3z / vl;
    const float aw = fmaxf(nx * vx + ny * vy + nz * vz, 0.0f);

    // visibility via depth map
    int xc = (int)rintf(cx); xc = min(max(xc, 0), IMG_W - 1);
    int yc = (int)rintf(cy); yc = min(max(yc, 0), IMG_H - 1);
    const float d = __uint_as_float(g_depth[(size_t)b * HW + yc * IMG_W + xc]);
    const float vw = (c3z <= d + 1e-3f) ? aw : 0.0f;   // z<=inf subsumes isinf

    out_vw[p] = vw;
    out_c3[3 * p + 0] = c3x;
    out_c3[3 * p + 1] = c3y;
    out_c3[3 * p + 2] = c3z;

    // bilinear sampling params (mirror reference formula exactly)
    const float gx = cx / (float)(IMG_W - 1) * 2.0f - 1.0f;
    const float gy = cy / (float)(IMG_H - 1) * 2.0f - 1.0f;
    const float px = (gx + 1.0f) * 0.5f * (float)(WF - 1);
    const float py = (gy + 1.0f) * 0.5f * (float)(HF - 1);
    const float x0f = floorf(px), y0f = floorf(py);
    const float wx = px - x0f, wy = py - y0f;
    const int x0 = (int)x0f, y0 = (int)y0f;
    const int x1 = x0 + 1,   y1 = y0 + 1;

    const float okx0 = (x0 >= 0 && x0 < WF) ? 1.0f : 0.0f;
    const float okx1 = (x1 >= 0 && x1 < WF) ? 1.0f : 0.0f;
    const float oky0 = (y0 >= 0 && y0 < HF) ? 1.0f : 0.0f;
    const float oky1 = (y1 >= 0 && y1 < HF) ? 1.0f : 0.0f;

    float4 wv;
    wv.x = (1.0f - wx) * (1.0f - wy) * okx0 * oky0;
    wv.y = wx          * (1.0f - wy) * okx1 * oky0;
    wv.z = (1.0f - wx) * wy          * okx0 * oky1;
    wv.w = wx          * wy          * okx1 * oky1;

    const int x0c = min(max(x0, 0), WF - 1);
    const int x1c = min(max(x1, 0), WF - 1);
    const int y0c = min(max(y0, 0), HF - 1);
    const int y1c = min(max(y1, 0), HF - 1);

    // corner offsets in half-element units (pixel * CC), batch folded in
    const int bpix = b * FHW;
    int4 iv;
    iv.x = (bpix + y0c * WF + x0c) * CC;
    iv.y = (bpix + y0c * WF + x1c) * CC;
    iv.z = (bpix + y1c * WF + x0c) * CC;
    iv.w = (bpix + y1c * WF + x1c) * CC;

    s_idx[wl][lane] = iv;
    s_w[wl][lane]   = wv;
    __syncwarp();

    // ---- Phase 2: loop over the warp's 32 points ----
    // Each lane owns channels [lane*4, lane*4+4): uint2 = 4 fp16 per corner.
    float4* __restrict__ outf = (float4*)out_feats;
    const size_t pbase = (size_t)warp_id * 32;
    const int choff = lane * 4;

#pragma unroll 4
    for (int k = 0; k < 32; ++k) {
        const int4   j = s_idx[wl][k];   // LDS.128 broadcast
        const float4 a = s_w[wl][k];     // LDS.128 broadcast

        const uint2 f00 = *(const uint2*)(g_fmH + (size_t)j.x + choff);
        const uint2 f01 = *(const uint2*)(g_fmH + (size_t)j.y + choff);
        const uint2 f10 = *(const uint2*)(g_fmH + (size_t)j.z + choff);
        const uint2 f11 = *(const uint2*)(g_fmH + (size_t)j.w + choff);

        const float2 c00a = __half22float2(*(const __half2*)&f00.x);
        const float2 c00b = __half22float2(*(const __half2*)&f00.y);
        const float2 c01a = __half22float2(*(const __half2*)&f01.x);
        const float2 c01b = __half22float2(*(const __half2*)&f01.y);
        const float2 c10a = __half22float2(*(const __half2*)&f10.x);
        const float2 c10b = __half22float2(*(const __half2*)&f10.y);
        const float2 c11a = __half22float2(*(const __half2*)&f11.x);
        const float2 c11b = __half22float2(*(const __half2*)&f11.y);

        float4 o;
        o.x = a.x * c00a.x + a.y * c01a.x + a.z * c10a.x + a.w * c11a.x;
        o.y = a.x * c00a.y + a.y * c01a.y + a.z * c10a.y + a.w * c11a.y;
        o.z = a.x * c00b.x + a.y * c01b.x + a.z * c10b.x + a.w * c11b.x;
        o.w = a.x * c00b.y + a.y * c01b.y + a.z * c10b.y + a.w * c11b.y;

        outf[(pbase + k) * (CC / 4) + lane] = o;
    }
}

// ---------------------------------------------------------------------------
// Launch
// ---------------------------------------------------------------------------
extern "C" void kernel_launch(void* const* d_in, const int* in_sizes, int n_in,
                              void* d_out, int out_size) {
    const float* fm      = (const float*)d_in[0];
    const float* v2d     = (const float*)d_in[1];
    const float* v3d     = (const float*)d_in[2];
    const int*   parents = (const int*)d_in[3];
    const float* bary    = (const float*)d_in[4];
    (void)in_sizes; (void)n_in; (void)out_size;

    float* out_feats = (float*)d_out;                                   // B*N*C
    float* out_vw    = out_feats + (size_t)BB * NT * CC;                // B*N
    float* out_c3    = out_vw    + (size_t)BB * NT;                     // B*N*3

    // 0. pack vertex records
    pack_k<<<(BB * NV + 255) / 256, 256>>>(v2d, v3d);
    // 1. transpose + fp16 convert feature map into L2-resident scratch
    {
        dim3 grid(FHW / 32, CC / 32, BB);
        dim3 block(32, 8);
        transpose_k<<<grid, block>>>(fm);
    }
    // 2. depth init
    depth_init_k<<<(BB * HW + 255) / 256, 256>>>();
    // 3. depth scatter-min
    depth_scatter_k<<<(BB * NV + 255) / 256, 256>>>(v2d, v3d);
    // 4. main: one warp per 32 points
    {
        const int total_threads = BB * NT;       // 800000 = 25000 warps
        const int blocks = total_threads / 256;  // 3125
        main_k<<<blocks, 256>>>(parents, bary, out_feats, out_vw, out_c3);
    }
}

// round 6
// speedup vs baseline: 2.5834x; 1.1044x over previous
#include <cuda_runtime.h>
#include <cuda_fp16.h>
#include <cstdint>

// Problem constants (fixed by setup_inputs)
#define BB   4
#define CC   128
#define HF   128
#define WF   128
#define NV   10475
#define NT   200000
#define KB   20
#define IMG_H 512
#define IMG_W 512
#define HW   (IMG_H * IMG_W)
#define FHW  (HF * WF)

// Scratch
__device__ __half   g_fmH[(size_t)BB * FHW * CC];     // 16.8 MB transposed fp16 features
__device__ unsigned g_depth[(size_t)BB * HW];         // 4 MB depth map
// 32B vertex record: slot0 = (x2d,y2d,x3d,y3d), slot1.x = z3d. One 128B line per vertex.
__device__ float4   g_vr[(size_t)BB * NV * 2];

// ---------------------------------------------------------------------------
// Kernel 0: fused depth-init + vertex pack
// ---------------------------------------------------------------------------
__global__ void prep_k(const float* __restrict__ v2d,
                       const float* __restrict__ v3d) {
    int i = blockIdx.x * blockDim.x + threadIdx.x;
    if (i < BB * HW) g_depth[i] = 0x7f800000u;   // +inf bits
    if (i < BB * NV) {
        float4 r;
        r.x = v2d[2 * i];
        r.y = v2d[2 * i + 1];
        r.z = v3d[3 * i];
        r.w = v3d[3 * i + 1];
        g_vr[2 * i] = r;
        g_vr[2 * i + 1] = make_float4(v3d[3 * i + 2], 0.f, 0.f, 0.f);
    }
}

// ---------------------------------------------------------------------------
// Kernel 1: transpose (B,C,Hf*Wf) f32 -> (B,Hf*Wf,C) fp16, tiled via smem
// ---------------------------------------------------------------------------
__global__ void transpose_k(const float* __restrict__ fm) {
    __shared__ float tile[32][33];
    const int b  = blockIdx.z;
    const int p0 = blockIdx.x * 32;   // spatial block
    const int c0 = blockIdx.y * 32;   // channel block
    const int tx = threadIdx.x;
    const int ty = threadIdx.y;       // block (32, 8)

    const float* src = fm + (size_t)b * CC * FHW;
#pragma unroll
    for (int i = 0; i < 32; i += 8)
        tile[ty + i][tx] = src[(size_t)(c0 + ty + i) * FHW + (p0 + tx)];
    __syncthreads();
    __half* dst = g_fmH + (size_t)b * FHW * CC;
#pragma unroll
    for (int i = 0; i < 32; i += 8)
        dst[(size_t)(p0 + ty + i) * CC + (c0 + tx)] =
            __float2half_rn(tile[tx][ty + i]);
}

// ---------------------------------------------------------------------------
// Kernel 3: scatter-min z over rounded vertex pixels
// ---------------------------------------------------------------------------
__global__ void depth_scatter_k(const float* __restrict__ v2d,
                                const float* __restrict__ v3d) {
    int i = blockIdx.x * blockDim.x + threadIdx.x;   // i = b*NV + v
    if (i >= BB * NV) return;
    int b = i / NV;
    float x = v2d[2 * i];
    float y = v2d[2 * i + 1];
    int xi = (int)rintf(x);   // round-half-even, matches jnp.round
    int yi = (int)rintf(y);
    if (xi >= 0 && xi < IMG_W && yi >= 0 && yi < IMG_H) {
        float z = v3d[3 * i + 2];
        atomicMin(&g_depth[(size_t)b * HW + yi * IMG_W + xi], __float_as_uint(z));
    }
}

// ---------------------------------------------------------------------------
// Kernel 4: main — one warp per 32 points.
// Phase 1: per-lane scalar pipeline; params staged to smem (no shuffles).
// Phase 2: per point, each lane owns 4 channels and loads all 4 corners
//   itself (uint2 = 4 fp16 per corner) — zero cross-lane communication.
// ---------------------------------------------------------------------------
__global__ void __launch_bounds__(256)
main_k(const int*   __restrict__ parents,
       const float* __restrict__ bary,
       float* __restrict__ out_feats,   // (B,N,C)
       float* __restrict__ out_vw,      // (B,N)
       float* __restrict__ out_c3)      // (B,N,3)
{
    __shared__ int4   s_idx[8][32];   // per-warp per-point corner offsets (half-elem units)
    __shared__ float4 s_w[8][32];     // per-warp per-point bilinear weights
    __shared__ float  s_c3[8][96];    // per-warp centers3d staging

    const int warp_id = (blockIdx.x * blockDim.x + threadIdx.x) >> 5;
    const int wl      = (threadIdx.x >> 5);      // warp within block
    const int lane    = threadIdx.x & 31;
    const int p       = warp_id * 32 + lane;     // this lane's point
    const int b = p / NT;
    const int n = p - b * NT;

    // ---- Phase 1: per-lane scalar pipeline for point p ----
    const int p0 = __ldg(&parents[3 * n + 0]);
    const int p1 = __ldg(&parents[3 * n + 1]);
    const int p2 = __ldg(&parents[3 * n + 2]);
    const int r  = n % KB;
    const float w0 = __ldg(&bary[3 * r + 0]);
    const float w1 = __ldg(&bary[3 * r + 1]);
    const float w2 = __ldg(&bary[3 * r + 2]);

    const int bnv = b * NV;
    const float4 V0 = __ldg(&g_vr[2 * (bnv + p0)]);
    const float4 V1 = __ldg(&g_vr[2 * (bnv + p1)]);
    const float4 V2 = __ldg(&g_vr[2 * (bnv + p2)]);
    // z sits in the same 128B line as the record -> L1 hit
    const float a0z = __ldg((const float*)&g_vr[2 * (bnv + p0) + 1]);
    const float a1z = __ldg((const float*)&g_vr[2 * (bnv + p1) + 1]);
    const float a2z = __ldg((const float*)&g_vr[2 * (bnv + p2) + 1]);

    const float cx = w0 * V0.x + w1 * V1.x + w2 * V2.x;
    const float cy = w0 * V0.y + w1 * V1.y + w2 * V2.y;

    const float a0x = V0.z, a0y = V0.w;
    const float a1x = V1.z, a1y = V1.w;
    const float a2x = V2.z, a2y = V2.w;
    const float c3x = w0 * a0x + w1 * a1x + w2 * a2x;
    const float c3y = w0 * a0y + w1 * a1y + w2 * a2y;
    const float c3z = w0 * a0z + w1 * a1z + w2 * a2z;

    // face normal & angle weight
    const float e1x = a1x - a0x, e1y = a1y - a0y, e1z = a1z - a0z;
    const float e2x = a2x - a0x, e2y = a2y - a0y, e2z = a2z - a0z;
    float nx = e1y * e2z - e1z * e2y;
    float ny = e1z * e2x - e1x * e2z;
    float nz = e1x * e2y - e1y * e2x;
    const float nl = sqrtf(nx * nx + ny * ny + nz * nz) + 1e-8f;
    nx /= nl; ny /= nl; nz /= nl;
    const float vl = sqrtf(c3x * c3x + c3y * c3y + c3z * c3z) + 1e-8f;
    const float vx = -c3x / vl, vy = -c3y / vl, vz = -c3z / vl;
    const float aw = fmaxf(nx * vx + ny * vy + nz * vz, 0.0f);

    // visibility via depth map
    int xc = (int)rintf(cx); xc = min(max(xc, 0), IMG_W - 1);
    int yc = (int)rintf(cy); yc = min(max(yc, 0), IMG_H - 1);
    const float d = __uint_as_float(g_depth[(size_t)b * HW + yc * IMG_W + xc]);
    const float vw = (c3z <= d + 1e-3f) ? aw : 0.0f;   // z<=inf subsumes isinf

    out_vw[p] = vw;
    // stage centers3d to smem, write coalesced below
    s_c3[wl][lane * 3 + 0] = c3x;
    s_c3[wl][lane * 3 + 1] = c3y;
    s_c3[wl][lane * 3 + 2] = c3z;

    // bilinear sampling params (mirror reference formula exactly)
    const float gx = cx / (float)(IMG_W - 1) * 2.0f - 1.0f;
    const float gy = cy / (float)(IMG_H - 1) * 2.0f - 1.0f;
    const float px = (gx + 1.0f) * 0.5f * (float)(WF - 1);
    const float py = (gy + 1.0f) * 0.5f * (float)(HF - 1);
    const float x0f = floorf(px), y0f = floorf(py);
    const float wx = px - x0f, wy = py - y0f;
    const int x0 = (int)x0f, y0 = (int)y0f;
    const int x1 = x0 + 1,   y1 = y0 + 1;

    const float okx0 = (x0 >= 0 && x0 < WF) ? 1.0f : 0.0f;
    const float okx1 = (x1 >= 0 && x1 < WF) ? 1.0f : 0.0f;
    const float oky0 = (y0 >= 0 && y0 < HF) ? 1.0f : 0.0f;
    const float oky1 = (y1 >= 0 && y1 < HF) ? 1.0f : 0.0f;

    float4 wv;
    wv.x = (1.0f - wx) * (1.0f - wy) * okx0 * oky0;
    wv.y = wx          * (1.0f - wy) * okx1 * oky0;
    wv.z = (1.0f - wx) * wy          * okx0 * oky1;
    wv.w = wx          * wy          * okx1 * oky1;

    const int x0c = min(max(x0, 0), WF - 1);
    const int x1c = min(max(x1, 0), WF - 1);
    const int y0c = min(max(y0, 0), HF - 1);
    const int y1c = min(max(y1, 0), HF - 1);

    // corner offsets in half-element units (pixel * CC), batch folded in
    const int bpix = b * FHW;
    int4 iv;
    iv.x = (bpix + y0c * WF + x0c) * CC;
    iv.y = (bpix + y0c * WF + x1c) * CC;
    iv.z = (bpix + y1c * WF + x0c) * CC;
    iv.w = (bpix + y1c * WF + x1c) * CC;

    s_idx[wl][lane] = iv;
    s_w[wl][lane]   = wv;
    __syncwarp();

    // coalesced centers3d store: warp covers 96 consecutive floats
    {
        float* dst = out_c3 + (size_t)warp_id * 96;
        dst[lane]      = s_c3[wl][lane];
        dst[lane + 32] = s_c3[wl][lane + 32];
        dst[lane + 64] = s_c3[wl][lane + 64];
    }

    // ---- Phase 2: loop over the warp's 32 points ----
    // Each lane owns channels [lane*4, lane*4+4): uint2 = 4 fp16 per corner.
    float4* __restrict__ outf = (float4*)out_feats;
    const size_t pbase = (size_t)warp_id * 32;
    const int choff = lane * 4;

#pragma unroll 8
    for (int k = 0; k < 32; ++k) {
        const int4   j = s_idx[wl][k];   // LDS.128 broadcast
        const float4 a = s_w[wl][k];     // LDS.128 broadcast

        const uint2 f00 = *(const uint2*)(g_fmH + (size_t)j.x + choff);
        const uint2 f01 = *(const uint2*)(g_fmH + (size_t)j.y + choff);
        const uint2 f10 = *(const uint2*)(g_fmH + (size_t)j.z + choff);
        const uint2 f11 = *(const uint2*)(g_fmH + (size_t)j.w + choff);

        const float2 c00a = __half22float2(*(const __half2*)&f00.x);
        const float2 c00b = __half22float2(*(const __half2*)&f00.y);
        const float2 c01a = __half22float2(*(const __half2*)&f01.x);
        const float2 c01b = __half22float2(*(const __half2*)&f01.y);
        const float2 c10a = __half22float2(*(const __half2*)&f10.x);
        const float2 c10b = __half22float2(*(const __half2*)&f10.y);
        const float2 c11a = __half22float2(*(const __half2*)&f11.x);
        const float2 c11b = __half22float2(*(const __half2*)&f11.y);

        float4 o;
        o.x = a.x * c00a.x + a.y * c01a.x + a.z * c10a.x + a.w * c11a.x;
        o.y = a.x * c00a.y + a.y * c01a.y + a.z * c10a.y + a.w * c11a.y;
        o.z = a.x * c00b.x + a.y * c01b.x + a.z * c10b.x + a.w * c11b.x;
        o.w = a.x * c00b.y + a.y * c01b.y + a.z * c10b.y + a.w * c11b.y;

        // streaming store: keep L2 for the feature map
        __stcs(&outf[(pbase + k) * (CC / 4) + lane], o);
    }
}

// ---------------------------------------------------------------------------
// Launch
// ---------------------------------------------------------------------------
extern "C" void kernel_launch(void* const* d_in, const int* in_sizes, int n_in,
                              void* d_out, int out_size) {
    const float* fm      = (const float*)d_in[0];
    const float* v2d     = (const float*)d_in[1];
    const float* v3d     = (const float*)d_in[2];
    const int*   parents = (const int*)d_in[3];
    const float* bary    = (const float*)d_in[4];
    (void)in_sizes; (void)n_in; (void)out_size;

    float* out_feats = (float*)d_out;                                   // B*N*C
    float* out_vw    = out_feats + (size_t)BB * NT * CC;                // B*N
    float* out_c3    = out_vw    + (size_t)BB * NT;                     // B*N*3

    // 0. fused depth-init + vertex pack
    prep_k<<<(BB * HW + 255) / 256, 256>>>(v2d, v3d);
    // 1. transpose + fp16 convert feature map into L2-resident scratch
    {
        dim3 grid(FHW / 32, CC / 32, BB);
        dim3 block(32, 8);
        transpose_k<<<grid, block>>>(fm);
    }
    // 3. depth scatter-min
    depth_scatter_k<<<(BB * NV + 255) / 256, 256>>>(v2d, v3d);
    // 4. main: one warp per 32 points
    {
        const int total_threads = BB * NT;       // 800000 = 25000 warps
        const int blocks = total_threads / 256;  // 3125
        main_k<<<blocks, 256>>>(parents, bary, out_feats, out_vw, out_c3);
    }
}